// round 5
// baseline (speedup 1.0000x reference)
#include <cuda_runtime.h>
#include <math.h>
#include <stdint.h>

#define B_  4
#define H_  16
#define LQ_ 512
#define LK_ 2048
#define DM_ 1024
#define DH_ 64

#define WSZ (512 * 1024)          // one converted W matrix (u32 kpairs x n)
#define XQ_OFF 0                  // converted X offsets (rows of 512 kpairs)
#define XK_OFF ((size_t)2048 * 512)
#define XV_OFF ((size_t)(2048 + 8192) * 512)

// Scratch (device globals; no runtime allocation allowed)
__device__ uint32_t g_wh [4 * WSZ];                 // W hi  [mat][kpair][1024]
__device__ uint32_t g_wl [4 * WSZ];                 // W lo
__device__ uint32_t g_xh [(size_t)18432 * 512];     // X hi  [row][kpair]
__device__ uint32_t g_xl [(size_t)18432 * 512];     // X lo
__device__ uint32_t g_qh [(size_t)B_*H_*LQ_*32];    // q hi  [b,h,l,dpair]
__device__ uint32_t g_ql [(size_t)B_*H_*LQ_*32];
__device__ uint32_t g_kth[(size_t)B_*H_*32*LK_];    // k hi transposed [b,h,dpair,key]
__device__ uint32_t g_ktl[(size_t)B_*H_*32*LK_];
__device__ uint32_t g_vth[(size_t)B_*H_*32*LK_];    // v hi transposed [b,h,dpair,key]
__device__ uint32_t g_vtl[(size_t)B_*H_*32*LK_];
__device__ uint32_t g_aoh[(size_t)B_*LQ_*512];      // attn out hi [row][dpair]
__device__ uint32_t g_aol[(size_t)B_*LQ_*512];
__device__ float    g_y  [(size_t)B_*LQ_*DM_];      // pre-LN

// ---------------------------------------------------------------------------
// bf16 helpers
// ---------------------------------------------------------------------------
__device__ __forceinline__ uint32_t packbf(float e, float o) {
    uint32_t r;
    asm("cvt.rn.bf16x2.f32 %0, %1, %2;" : "=r"(r) : "f"(o), "f"(e));
    return r;
}
__device__ __forceinline__ float lo16f(uint32_t h) { return __uint_as_float(h << 16); }
__device__ __forceinline__ float hi16f(uint32_t h) { return __uint_as_float(h & 0xffff0000u); }

__device__ __forceinline__ void split2(float x, float y, uint32_t& hi, uint32_t& lo) {
    hi = packbf(x, y);
    lo = packbf(x - lo16f(hi), y - hi16f(hi));
}

__device__ __forceinline__ void mma_bf16(float c[4],
                                         uint32_t a0, uint32_t a1, uint32_t a2, uint32_t a3,
                                         uint32_t b0, uint32_t b1)
{
    asm volatile(
        "mma.sync.aligned.m16n8k16.row.col.f32.bf16.bf16.f32 "
        "{%0,%1,%2,%3}, {%4,%5,%6,%7}, {%8,%9}, {%0,%1,%2,%3};"
        : "+f"(c[0]), "+f"(c[1]), "+f"(c[2]), "+f"(c[3])
        : "r"(a0), "r"(a1), "r"(a2), "r"(a3), "r"(b0), "r"(b1));
}

// ---------------------------------------------------------------------------
// Pre-pass: convert X rows (pairs along contiguous k)
// ---------------------------------------------------------------------------
__global__ void convert_x(const float* __restrict__ src,
                          uint32_t* __restrict__ dh, uint32_t* __restrict__ dl)
{
    int t = blockIdx.x * 256 + threadIdx.x;
    float4 v = ((const float4*)src)[t];
    uint32_t h0, l0, h1, l1;
    split2(v.x, v.y, h0, l0);
    split2(v.z, v.w, h1, l1);
    uint2 hh = {h0, h1}, ll = {l0, l1};
    ((uint2*)dh)[t] = hh;
    ((uint2*)dl)[t] = ll;
}

// Pre-pass: convert W (pairs across adjacent k rows) -> [kpair][1024]
__global__ void convert_w(const float* __restrict__ src,
                          uint32_t* __restrict__ dh, uint32_t* __restrict__ dl)
{
    int t = blockIdx.x * 256 + threadIdx.x;      // 512*256 threads
    int p = t >> 8, n4 = (t & 255) * 4;
    float4 r0 = *(const float4*)&src[(size_t)(2 * p) * DM_ + n4];
    float4 r1 = *(const float4*)&src[(size_t)(2 * p + 1) * DM_ + n4];
    uint4 h, l;
    split2(r0.x, r1.x, h.x, l.x);
    split2(r0.y, r1.y, h.y, l.y);
    split2(r0.z, r1.z, h.z, l.z);
    split2(r0.w, r1.w, h.w, l.w);
    *(uint4*)&dh[(size_t)p * DM_ + n4] = h;
    *(uint4*)&dl[(size_t)p * DM_ + n4] = l;
}

// ---------------------------------------------------------------------------
// bf16 3-pass GEMM on pre-split operands.
// CTA 128x128, BK=32 (16 kpairs), 256 threads (8 warps 2x4), warp tile 64x32.
// outMode: 0 -> g_qh/ql, 1 -> g_kth/ktl, 2 -> g_vth/vtl, 3 -> g_y (+resid)
// ---------------------------------------------------------------------------
#define GS_XH 0
#define GS_XL (128 * 20)
#define GS_WH (2 * 128 * 20)
#define GS_WL (2 * 128 * 20 + 16 * 136)
#define GEMM_SMEM ((2 * 128 * 20 + 2 * 16 * 136) * 4)

__global__ __launch_bounds__(256)
void gemm_bf16(const uint32_t* __restrict__ Xh_g, const uint32_t* __restrict__ Xl_g,
               const uint32_t* __restrict__ Wh_g, const uint32_t* __restrict__ Wl_g,
               const float* __restrict__ bias,
               const float* __restrict__ resid,
               int L, int outMode)
{
    extern __shared__ uint32_t sm[];
    uint32_t* Xh = sm + GS_XH;
    uint32_t* Xl = sm + GS_XL;
    uint32_t* Wh = sm + GS_WH;
    uint32_t* Wl = sm + GS_WL;

    const int row0 = blockIdx.y * 128;
    const int col0 = blockIdx.x * 128;
    const int tid  = threadIdx.x;
    const int lane = tid & 31;
    const int w    = tid >> 5;
    const int wm   = (w >> 2) * 64;
    const int wn   = (w & 3) * 32;
    const int grp  = lane >> 2;
    const int tg   = lane & 3;

    float acc[4][4][4] = {};

    const int xm  = tid >> 1;            // 0..127
    const int xo  = (tid & 1) * 2;       // uint4 slots {0,1} or {2,3}
    const int wkp = tid >> 4;            // 0..15
    const int wn0 = (tid & 15) * 8;      // 0..120

    for (int kp0 = 0; kp0 < DM_ / 2; kp0 += 16) {
        // ---- fill X tile [128 rows][16 kpairs] ----
        #pragma unroll
        for (int i = 0; i < 2; i++) {
            int off = (xo + i) * 4;
            *(uint4*)&Xh[xm * 20 + off] = *(const uint4*)&Xh_g[(size_t)(row0 + xm) * 512 + kp0 + off];
            *(uint4*)&Xl[xm * 20 + off] = *(const uint4*)&Xl_g[(size_t)(row0 + xm) * 512 + kp0 + off];
        }
        // ---- fill W tile [16 kpairs][128 n] ----
        {
            const size_t gbase = (size_t)(kp0 + wkp) * DM_ + col0 + wn0;
            *(uint4*)&Wh[wkp * 136 + wn0]     = *(const uint4*)&Wh_g[gbase];
            *(uint4*)&Wh[wkp * 136 + wn0 + 4] = *(const uint4*)&Wh_g[gbase + 4];
            *(uint4*)&Wl[wkp * 136 + wn0]     = *(const uint4*)&Wl_g[gbase];
            *(uint4*)&Wl[wkp * 136 + wn0 + 4] = *(const uint4*)&Wl_g[gbase + 4];
        }
        __syncthreads();

        #pragma unroll
        for (int kt = 0; kt < 2; kt++) {
            const int kb = kt * 8;
            uint32_t bh[4][2], bl[4][2];
            #pragma unroll
            for (int nt = 0; nt < 4; nt++) {
                int cc = wn + nt * 8 + grp;
                bh[nt][0] = Wh[(kb + tg) * 136 + cc];
                bh[nt][1] = Wh[(kb + tg + 4) * 136 + cc];
                bl[nt][0] = Wl[(kb + tg) * 136 + cc];
                bl[nt][1] = Wl[(kb + tg + 4) * 136 + cc];
            }
            #pragma unroll
            for (int m = 0; m < 4; m++) {
                int r = wm + m * 16 + grp;
                uint32_t ah0 = Xh[r * 20 + kb + tg];
                uint32_t ah1 = Xh[(r + 8) * 20 + kb + tg];
                uint32_t ah2 = Xh[r * 20 + kb + tg + 4];
                uint32_t ah3 = Xh[(r + 8) * 20 + kb + tg + 4];
                uint32_t al0 = Xl[r * 20 + kb + tg];
                uint32_t al1 = Xl[(r + 8) * 20 + kb + tg];
                uint32_t al2 = Xl[r * 20 + kb + tg + 4];
                uint32_t al3 = Xl[(r + 8) * 20 + kb + tg + 4];
                #pragma unroll
                for (int nt = 0; nt < 4; nt++) {
                    mma_bf16(acc[m][nt], ah0, ah1, ah2, ah3, bh[nt][0], bh[nt][1]);
                    mma_bf16(acc[m][nt], ah0, ah1, ah2, ah3, bl[nt][0], bl[nt][1]);
                    mma_bf16(acc[m][nt], al0, al1, al2, al3, bh[nt][0], bh[nt][1]);
                }
            }
        }
        __syncthreads();
    }

    // ---- epilogue ----
    #pragma unroll
    for (int nt = 0; nt < 4; nt++) {
        const int gc = col0 + wn + nt * 8 + tg * 2;
        const float b0 = bias[gc], b1 = bias[gc + 1];
        #pragma unroll
        for (int m = 0; m < 4; m++) {
            int r0 = row0 + wm + m * 16 + grp;
            int r1 = r0 + 8;
            float v00 = acc[m][nt][0] + b0, v01 = acc[m][nt][1] + b1;
            float v10 = acc[m][nt][2] + b0, v11 = acc[m][nt][3] + b1;
            if (outMode == 3) {
                float2 rr0 = *(const float2*)&resid[(size_t)r0 * DM_ + gc];
                float2 rr1 = *(const float2*)&resid[(size_t)r1 * DM_ + gc];
                float2 o0 = {v00 + rr0.x, v01 + rr0.y};
                float2 o1 = {v10 + rr1.x, v11 + rr1.y};
                *(float2*)&g_y[(size_t)r0 * DM_ + gc] = o0;
                *(float2*)&g_y[(size_t)r1 * DM_ + gc] = o1;
            } else {
                uint32_t h0, l0u, h1, l1u;
                split2(v00, v01, h0, l0u);
                split2(v10, v11, h1, l1u);
                int hh = gc >> 6, dp = (gc & 63) >> 1;
                int b0i = r0 / L, ll0 = r0 % L;
                int b1i = r1 / L, ll1 = r1 % L;
                if (outMode == 0) {
                    size_t i0 = ((size_t)(b0i * H_ + hh) * LQ_ + ll0) * 32 + dp;
                    size_t i1 = ((size_t)(b1i * H_ + hh) * LQ_ + ll1) * 32 + dp;
                    g_qh[i0] = h0; g_ql[i0] = l0u;
                    g_qh[i1] = h1; g_ql[i1] = l1u;
                } else {
                    uint32_t* oh = (outMode == 1) ? g_kth : g_vth;
                    uint32_t* ol = (outMode == 1) ? g_ktl : g_vtl;
                    size_t i0 = ((size_t)(b0i * H_ + hh) * 32 + dp) * LK_ + ll0;
                    size_t i1 = ((size_t)(b1i * H_ + hh) * 32 + dp) * LK_ + ll1;
                    oh[i0] = h0; ol[i0] = l0u;
                    oh[i1] = h1; ol[i1] = l1u;
                }
            }
        }
    }
}

// ---------------------------------------------------------------------------
// Tensor-core flash attention on pre-split q/k/v.
// Block = (64 q, h, b), 128 threads (4 warps), warp owns 16 q rows.
// Smem (u32 = bf16x2): Q [64 q][32 dpair] s36; K [32 dpair][64 key] s72;
// V [32 keypair][64 d] s72 (repacked via PRMT from transposed global).
// ---------------------------------------------------------------------------
#define FS_QH 0
#define FS_QL (64 * 36)
#define FS_KH (2 * 64 * 36)
#define FS_KL (2 * 64 * 36 + 32 * 72)
#define FS_VH (2 * 64 * 36 + 2 * 32 * 72)
#define FS_VL (2 * 64 * 36 + 3 * 32 * 72)
#define FS_MSK (2 * 64 * 36 + 4 * 32 * 72)
#define FA_SMEM ((FS_MSK + 64) * 4)

__global__ __launch_bounds__(128)
void flash_attn(const int* __restrict__ mask)
{
    extern __shared__ uint32_t sm[];
    uint32_t* Qh = sm + FS_QH;
    uint32_t* Ql = sm + FS_QL;
    uint32_t* Kh = sm + FS_KH;
    uint32_t* Kl = sm + FS_KL;
    uint32_t* Vh = sm + FS_VH;
    uint32_t* Vl = sm + FS_VL;
    float*   msk = (float*)(sm + FS_MSK);

    const int q0 = blockIdx.x * 64, h = blockIdx.y, b = blockIdx.z;
    const int tid  = threadIdx.x;
    const int lane = tid & 31;
    const int w    = tid >> 5;
    const int grp  = lane >> 2;
    const int tg   = lane & 3;

    const size_t bh_off = (size_t)(b * H_ + h);
    const uint32_t* qh_g = g_qh + (bh_off * LQ_ + q0) * 32;
    const uint32_t* ql_g = g_ql + (bh_off * LQ_ + q0) * 32;
    const uint32_t* kth  = g_kth + bh_off * 32 * LK_;
    const uint32_t* ktl  = g_ktl + bh_off * 32 * LK_;
    const uint32_t* vth  = g_vth + bh_off * 32 * LK_;
    const uint32_t* vtl  = g_vtl + bh_off * 32 * LK_;

    // ---- load Q tile (once): [q][dpair] straight copy ----
    {
        int q = tid >> 1, half = (tid & 1) * 16;
        #pragma unroll
        for (int i = 0; i < 4; i++) {
            *(uint4*)&Qh[q * 36 + half + i * 4] = *(const uint4*)&qh_g[(size_t)q * 32 + half + i * 4];
            *(uint4*)&Ql[q * 36 + half + i * 4] = *(const uint4*)&ql_g[(size_t)q * 32 + half + i * 4];
        }
    }

    float o[8][4];
    #pragma unroll
    for (int nt = 0; nt < 8; nt++)
        #pragma unroll
        for (int j = 0; j < 4; j++) o[nt][j] = 0.f;
    float m0 = -1e30f, m1 = -1e30f, l0 = 0.f, l1 = 0.f;

    const int dpr = tid >> 2;            // 0..31 (K and V fills)
    const int kq4 = (tid & 3) * 16;      // key base

    for (int t = 0; t < LK_ / 64; t++) {
        const int k0 = t * 64;
        __syncthreads();
        // ---- K tile: [dpair][key] coalesced copy ----
        #pragma unroll
        for (int i = 0; i < 4; i++) {
            *(uint4*)&Kh[dpr * 72 + kq4 + i * 4] = *(const uint4*)&kth[(size_t)dpr * LK_ + k0 + kq4 + i * 4];
            *(uint4*)&Kl[dpr * 72 + kq4 + i * 4] = *(const uint4*)&ktl[(size_t)dpr * LK_ + k0 + kq4 + i * 4];
        }
        // ---- V tile: repack d-pairs -> key-pairs via PRMT ----
        #pragma unroll
        for (int i = 0; i < 4; i++) {
            int key = kq4 + i * 4;
            uint4 ah = *(const uint4*)&vth[(size_t)dpr * LK_ + k0 + key];
            uint4 al = *(const uint4*)&vtl[(size_t)dpr * LK_ + k0 + key];
            uint2 pe0 = {__byte_perm(ah.x, ah.y, 0x5410), __byte_perm(ah.x, ah.y, 0x7632)};
            uint2 pe1 = {__byte_perm(ah.z, ah.w, 0x5410), __byte_perm(ah.z, ah.w, 0x7632)};
            *(uint2*)&Vh[(key >> 1) * 72 + 2 * dpr]       = pe0;
            *(uint2*)&Vh[((key >> 1) + 1) * 72 + 2 * dpr] = pe1;
            uint2 pl0 = {__byte_perm(al.x, al.y, 0x5410), __byte_perm(al.x, al.y, 0x7632)};
            uint2 pl1 = {__byte_perm(al.z, al.w, 0x5410), __byte_perm(al.z, al.w, 0x7632)};
            *(uint2*)&Vl[(key >> 1) * 72 + 2 * dpr]       = pl0;
            *(uint2*)&Vl[((key >> 1) + 1) * 72 + 2 * dpr] = pl1;
        }
        if (tid < 64) msk[tid] = (mask[b * LK_ + k0 + tid] == 0) ? -1e30f : 0.0f;
        __syncthreads();

        // ---- S = Q K^T (3-pass bf16) ----
        float s[8][4];
        #pragma unroll
        for (int nt = 0; nt < 8; nt++)
            #pragma unroll
            for (int j = 0; j < 4; j++) s[nt][j] = 0.f;

        const int r = w * 16 + grp;
        #pragma unroll
        for (int kt = 0; kt < 4; kt++) {
            const int kb = kt * 8;
            uint32_t ah0 = Qh[r * 36 + kb + tg];
            uint32_t ah1 = Qh[(r + 8) * 36 + kb + tg];
            uint32_t ah2 = Qh[r * 36 + kb + tg + 4];
            uint32_t ah3 = Qh[(r + 8) * 36 + kb + tg + 4];
            uint32_t al0 = Ql[r * 36 + kb + tg];
            uint32_t al1 = Ql[(r + 8) * 36 + kb + tg];
            uint32_t al2 = Ql[r * 36 + kb + tg + 4];
            uint32_t al3 = Ql[(r + 8) * 36 + kb + tg + 4];
            #pragma unroll
            for (int nt = 0; nt < 8; nt++) {
                int cc = nt * 8 + grp;
                uint32_t bh0 = Kh[(kb + tg) * 72 + cc];
                uint32_t bh1 = Kh[(kb + tg + 4) * 72 + cc];
                uint32_t bl0 = Kl[(kb + tg) * 72 + cc];
                uint32_t bl1 = Kl[(kb + tg + 4) * 72 + cc];
                mma_bf16(s[nt], ah0, ah1, ah2, ah3, bh0, bh1);
                mma_bf16(s[nt], ah0, ah1, ah2, ah3, bl0, bl1);
                mma_bf16(s[nt], al0, al1, al2, al3, bh0, bh1);
            }
        }

        // ---- online softmax ----
        const float scl = 0.125f;
        float rmax0 = -1e30f, rmax1 = -1e30f;
        #pragma unroll
        for (int nt = 0; nt < 8; nt++) {
            float mk0 = msk[nt * 8 + 2 * tg];
            float mk1 = msk[nt * 8 + 2 * tg + 1];
            s[nt][0] = s[nt][0] * scl + mk0;
            s[nt][1] = s[nt][1] * scl + mk1;
            s[nt][2] = s[nt][2] * scl + mk0;
            s[nt][3] = s[nt][3] * scl + mk1;
            rmax0 = fmaxf(rmax0, fmaxf(s[nt][0], s[nt][1]));
            rmax1 = fmaxf(rmax1, fmaxf(s[nt][2], s[nt][3]));
        }
        rmax0 = fmaxf(rmax0, __shfl_xor_sync(0xffffffffu, rmax0, 1));
        rmax0 = fmaxf(rmax0, __shfl_xor_sync(0xffffffffu, rmax0, 2));
        rmax1 = fmaxf(rmax1, __shfl_xor_sync(0xffffffffu, rmax1, 1));
        rmax1 = fmaxf(rmax1, __shfl_xor_sync(0xffffffffu, rmax1, 2));

        float mn0 = fmaxf(m0, rmax0), mn1 = fmaxf(m1, rmax1);
        float c0 = __expf(m0 - mn0),  c1 = __expf(m1 - mn1);
        m0 = mn0; m1 = mn1;

        float sum0 = 0.f, sum1 = 0.f;
        #pragma unroll
        for (int nt = 0; nt < 8; nt++) {
            s[nt][0] = __expf(s[nt][0] - mn0);
            s[nt][1] = __expf(s[nt][1] - mn0);
            s[nt][2] = __expf(s[nt][2] - mn1);
            s[nt][3] = __expf(s[nt][3] - mn1);
            sum0 += s[nt][0] + s[nt][1];
            sum1 += s[nt][2] + s[nt][3];
        }
        sum0 += __shfl_xor_sync(0xffffffffu, sum0, 1);
        sum0 += __shfl_xor_sync(0xffffffffu, sum0, 2);
        sum1 += __shfl_xor_sync(0xffffffffu, sum1, 1);
        sum1 += __shfl_xor_sync(0xffffffffu, sum1, 2);
        l0 = l0 * c0 + sum0;
        l1 = l1 * c1 + sum1;

        #pragma unroll
        for (int nt = 0; nt < 8; nt++) {
            o[nt][0] *= c0; o[nt][1] *= c0;
            o[nt][2] *= c1; o[nt][3] *= c1;
        }

        // ---- O += P V (P split in regs, 3-pass) ----
        #pragma unroll
        for (int kg = 0; kg < 4; kg++) {
            uint32_t ph0, ph1, ph2, ph3, pl0, pl1, pl2, pl3;
            split2(s[2 * kg][0],     s[2 * kg][1],     ph0, pl0);
            split2(s[2 * kg][2],     s[2 * kg][3],     ph1, pl1);
            split2(s[2 * kg + 1][0], s[2 * kg + 1][1], ph2, pl2);
            split2(s[2 * kg + 1][2], s[2 * kg + 1][3], ph3, pl3);
            #pragma unroll
            for (int nt = 0; nt < 8; nt++) {
                int cc = nt * 8 + grp;
                uint32_t bh0 = Vh[(kg * 8 + tg) * 72 + cc];
                uint32_t bh1 = Vh[(kg * 8 + tg + 4) * 72 + cc];
                uint32_t bl0 = Vl[(kg * 8 + tg) * 72 + cc];
                uint32_t bl1 = Vl[(kg * 8 + tg + 4) * 72 + cc];
                mma_bf16(o[nt], ph0, ph1, ph2, ph3, bh0, bh1);
                mma_bf16(o[nt], ph0, ph1, ph2, ph3, bl0, bl1);
                mma_bf16(o[nt], pl0, pl1, pl2, pl3, bh0, bh1);
            }
        }
    }

    // ---- epilogue: write packed hi/lo attention output ----
    float inv0 = 1.0f / l0, inv1 = 1.0f / l1;
    int qr0 = q0 + w * 16 + grp;
    int qr1 = qr0 + 8;
    size_t r0base = ((size_t)b * LQ_ + qr0) * 512 + h * 32;
    size_t r1base = ((size_t)b * LQ_ + qr1) * 512 + h * 32;
    #pragma unroll
    for (int nt = 0; nt < 8; nt++) {
        int dp = nt * 4 + tg;
        uint32_t hh, ll;
        split2(o[nt][0] * inv0, o[nt][1] * inv0, hh, ll);
        g_aoh[r0base + dp] = hh;
        g_aol[r0base + dp] = ll;
        split2(o[nt][2] * inv1, o[nt][3] * inv1, hh, ll);
        g_aoh[r1base + dp] = hh;
        g_aol[r1base + dp] = ll;
    }
}

// ---------------------------------------------------------------------------
// LayerNorm per row of g_y
// ---------------------------------------------------------------------------
__global__ void layernorm_kernel(const float* __restrict__ gamma,
                                 const float* __restrict__ beta,
                                 float* __restrict__ out)
{
    const int row = blockIdx.x;
    const int tid = threadIdx.x;
    __shared__ float red[256];

    const float* yr = g_y + (size_t)row * DM_;
    float4 xv = *(const float4*)(yr + tid * 4);

    float s = xv.x + xv.y + xv.z + xv.w;
    red[tid] = s; __syncthreads();
    #pragma unroll
    for (int st = 128; st > 0; st >>= 1) {
        if (tid < st) red[tid] += red[tid + st];
        __syncthreads();
    }
    float mean = red[0] * (1.0f / DM_);
    __syncthreads();

    float dx = xv.x - mean, dy = xv.y - mean, dz = xv.z - mean, dw = xv.w - mean;
    float sq = dx * dx + dy * dy + dz * dz + dw * dw;
    red[tid] = sq; __syncthreads();
    #pragma unroll
    for (int st = 128; st > 0; st >>= 1) {
        if (tid < st) red[tid] += red[tid + st];
        __syncthreads();
    }
    float rstd = rsqrtf(red[0] * (1.0f / DM_) + 1e-5f);

    int n = tid * 4;
    float4 ov;
    ov.x = dx * rstd * gamma[n]     + beta[n];
    ov.y = dy * rstd * gamma[n + 1] + beta[n + 1];
    ov.z = dz * rstd * gamma[n + 2] + beta[n + 2];
    ov.w = dw * rstd * gamma[n + 3] + beta[n + 3];
    *(float4*)(out + (size_t)row * DM_ + n) = ov;
}

// ---------------------------------------------------------------------------
extern "C" void kernel_launch(void* const* d_in, const int* in_sizes, int n_in,
                              void* d_out, int out_size)
{
    const float* Q    = (const float*)d_in[0];
    const float* K    = (const float*)d_in[1];
    const float* V    = (const float*)d_in[2];
    /* d_in[3] = node_num (unused) */
    const int*   mask = (const int*)  d_in[4];
    const float* Wq   = (const float*)d_in[5];
    const float* bq   = (const float*)d_in[6];
    const float* Wk   = (const float*)d_in[7];
    const float* bk   = (const float*)d_in[8];
    const float* Wv   = (const float*)d_in[9];
    const float* bv   = (const float*)d_in[10];
    const float* Wo   = (const float*)d_in[11];
    const float* bo   = (const float*)d_in[12];
    const float* gamma= (const float*)d_in[13];
    const float* beta = (const float*)d_in[14];
    float* out = (float*)d_out;

    cudaFuncSetAttribute(gemm_bf16,  cudaFuncAttributeMaxDynamicSharedMemorySize, GEMM_SMEM);
    cudaFuncSetAttribute(flash_attn, cudaFuncAttributeMaxDynamicSharedMemorySize, FA_SMEM);

    uint32_t *wh, *wl, *xh, *xl, *aoh, *aol;
    cudaGetSymbolAddress((void**)&wh,  g_wh);
    cudaGetSymbolAddress((void**)&wl,  g_wl);
    cudaGetSymbolAddress((void**)&xh,  g_xh);
    cudaGetSymbolAddress((void**)&xl,  g_xl);
    cudaGetSymbolAddress((void**)&aoh, g_aoh);
    cudaGetSymbolAddress((void**)&aol, g_aol);

    // ---- pre-pass conversions ----
    convert_w<<<512, 256>>>(Wq, wh + 0 * WSZ, wl + 0 * WSZ);
    convert_w<<<512, 256>>>(Wk, wh + 1 * WSZ, wl + 1 * WSZ);
    convert_w<<<512, 256>>>(Wv, wh + 2 * WSZ, wl + 2 * WSZ);
    convert_w<<<512, 256>>>(Wo, wh + 3 * WSZ, wl + 3 * WSZ);
    convert_x<<<2048, 256>>>(Q, xh + XQ_OFF, xl + XQ_OFF);
    convert_x<<<8192, 256>>>(K, xh + XK_OFF, xl + XK_OFF);
    convert_x<<<8192, 256>>>(V, xh + XV_OFF, xl + XV_OFF);

    // ---- projections ----
    gemm_bf16<<<dim3(8, 16), 256, GEMM_SMEM>>>(xh + XQ_OFF, xl + XQ_OFF, wh + 0 * WSZ, wl + 0 * WSZ, bq, nullptr, LQ_, 0);
    gemm_bf16<<<dim3(8, 64), 256, GEMM_SMEM>>>(xh + XK_OFF, xl + XK_OFF, wh + 1 * WSZ, wl + 1 * WSZ, bk, nullptr, LK_, 1);
    gemm_bf16<<<dim3(8, 64), 256, GEMM_SMEM>>>(xh + XV_OFF, xl + XV_OFF, wh + 2 * WSZ, wl + 2 * WSZ, bv, nullptr, LK_, 2);

    // ---- attention ----
    flash_attn<<<dim3(LQ_ / 64, H_, B_), 128, FA_SMEM>>>(mask);

    // ---- output projection + residual ----
    gemm_bf16<<<dim3(8, 16), 256, GEMM_SMEM>>>(aoh, aol, wh + 3 * WSZ, wl + 3 * WSZ, bo, Q, LQ_, 3);

    // ---- layernorm ----
    layernorm_kernel<<<B_ * LQ_, 256>>>(gamma, beta, out);
}